// round 1
// baseline (speedup 1.0000x reference)
#include <cuda_runtime.h>
#include <math.h>
#include <float.h>

#define Bsz 2
#define Mdim 2048
#define Ndim 2048
#define Ddim 32
#define Kk 32
#define Hh 4
#define DHh 8
#define Ff 8
#define Gg 60

// ---- scratch (no allocations allowed) ----
__device__ int   g_knn[Bsz * Mdim * Kk];
__device__ float g_h[Bsz * 64 * Mdim];
__device__ float g_attn[Bsz * 32 * Mdim];
__device__ float g_mean[Bsz * 64];
__device__ float g_istd[Bsz * 64];

// ===================== Kernel 1: score GEMM + top-K =====================
#define TM 8
#define TN 128
__global__ void k1_score_topk(const float* __restrict__ src, const float* __restrict__ tgt)
{
    extern __shared__ float sm[];
    float* s_scores = sm;               // TM * Ndim
    float* s_tile   = sm + TM * Ndim;   // Ddim * TN

    const int b    = blockIdx.y;
    const int m0   = blockIdx.x * TM;
    const int w    = threadIdx.x >> 5;
    const int lane = threadIdx.x & 31;
    const int m    = m0 + w;

    // source row for this warp's m (broadcast loads)
    float rsrc[Ddim];
#pragma unroll
    for (int d = 0; d < Ddim; d++)
        rsrc[d] = src[((size_t)b * Ddim + d) * Mdim + m];

    for (int t = 0; t < Ndim / TN; t++) {
        const int n0 = t * TN;
        for (int i = threadIdx.x; i < Ddim * TN; i += blockDim.x) {
            int d = i / TN, nn = i % TN;
            s_tile[i] = tgt[((size_t)b * Ddim + d) * Ndim + n0 + nn];
        }
        __syncthreads();

        float4 acc = make_float4(0.f, 0.f, 0.f, 0.f);
        const float4* tile4 = (const float4*)s_tile;
#pragma unroll
        for (int d = 0; d < Ddim; d++) {
            float4 tv = tile4[d * (TN / 4) + lane];
            acc.x += rsrc[d] * tv.x; acc.y += rsrc[d] * tv.y;
            acc.z += rsrc[d] * tv.z; acc.w += rsrc[d] * tv.w;
        }
        ((float4*)(s_scores + w * Ndim + n0))[lane] = acc;
        __syncthreads();
    }

    // top-K: iterative warp argmax over warp-private smem row.
    // Lane scans strided segment (idx % 32 == lane) -> conflict-free LDS.
    // Tie-break: smaller index wins (matches stable jax.lax.top_k).
    float* ws = s_scores + w * Ndim;
    for (int it = 0; it < Kk; it++) {
        float best = -FLT_MAX;
        int   bidx = 0x7fffffff;
        for (int j = 0; j < Ndim / 32; j++) {
            int idx = j * 32 + lane;
            float v = ws[idx];
            if (v > best) { best = v; bidx = idx; }
        }
#pragma unroll
        for (int off = 16; off; off >>= 1) {
            float ov = __shfl_down_sync(0xffffffffu, best, off);
            int   oi = __shfl_down_sync(0xffffffffu, bidx, off);
            if (ov > best || (ov == best && oi < bidx)) { best = ov; bidx = oi; }
        }
        bidx = __shfl_sync(0xffffffffu, bidx, 0);
        if ((bidx & 31) == lane) ws[bidx] = -FLT_MAX;
        if (lane == 0) g_knn[((size_t)b * Mdim + m) * Kk + it] = bidx;
        __syncwarp();
    }
}

// ===================== Kernel 2: kNN attention + MLP stage 1 =====================
__global__ void k2_attention(const float* __restrict__ src, const float* __restrict__ tgt,
                             const float* __restrict__ finv,
                             const float* __restrict__ wq, const float* __restrict__ bq,
                             const float* __restrict__ wk, const float* __restrict__ bk,
                             const float* __restrict__ wv, const float* __restrict__ bv,
                             const float* __restrict__ wm, const float* __restrict__ bm,
                             const float* __restrict__ w1, const float* __restrict__ b1)
{
    const int m = blockIdx.x, b = blockIdx.y;
    const int tid = threadIdx.x;

    __shared__ float s_feat[Kk * Ddim];       // [k][d], stride 32 (broadcast reads)
    __shared__ float s_kv[Kk * 33];           // [k][d], pad 33 (strided head reads)
    __shared__ float s_vv[Kk * 33];
    __shared__ float s_q[Ddim];
    __shared__ float s_p[Hh * Kk];
    __shared__ float s_xp[4 * Ddim];
    __shared__ float s_cat[96];
    __shared__ int   s_idx[Kk];

    if (tid < Kk) s_idx[tid] = g_knn[((size_t)b * Mdim + m) * Kk + tid];
    if (tid < 32) s_cat[32 + tid] = src[((size_t)b * Ddim + tid) * Mdim + m];
    if (tid >= 32 && tid < 64) s_cat[tid - 32] = finv[((size_t)b * Ddim + (tid - 32)) * Mdim + m];
    __syncthreads();

    for (int i = tid; i < Kk * Ddim; i += blockDim.x) {
        int k = i >> 5, d = i & 31;
        s_feat[k * Ddim + d] = tgt[((size_t)b * Ddim + d) * Ndim + s_idx[k]];
    }
    __syncthreads();

    const int d = tid & 31;
    const int part = tid >> 5;   // 0..3 (== warp id)

    if (part == 0) {
        float acc = bq[d];
#pragma unroll
        for (int i = 0; i < Ddim; i++) acc += wq[d * Ddim + i] * s_cat[32 + i];
        s_q[d] = acc;
    }
    {
        float wrow[Ddim];
#pragma unroll
        for (int i = 0; i < Ddim; i++) wrow[i] = wk[d * Ddim + i];
        float bias = bk[d];
#pragma unroll
        for (int j = 0; j < 8; j++) {
            int k = part * 8 + j;
            float acc = bias;
#pragma unroll
            for (int i = 0; i < Ddim; i++) acc += wrow[i] * s_feat[k * Ddim + i];
            s_kv[k * 33 + d] = acc;
        }
#pragma unroll
        for (int i = 0; i < Ddim; i++) wrow[i] = wv[d * Ddim + i];
        bias = bv[d];
#pragma unroll
        for (int j = 0; j < 8; j++) {
            int k = part * 8 + j;
            float acc = bias;
#pragma unroll
            for (int i = 0; i < Ddim; i++) acc += wrow[i] * s_feat[k * Ddim + i];
            s_vv[k * 33 + d] = acc;
        }
    }
    __syncthreads();

    // scores + softmax: warp h owns head h, lane = k
    {
        const int h = part;
        const int k = d;
        float sc = 0.f;
#pragma unroll
        for (int dh = 0; dh < DHh; dh++)
            sc += s_q[dh * Hh + h] * s_kv[k * 33 + dh * Hh + h];
        sc *= 0.3535533905932738f;   // 1/sqrt(8)
        float mx = sc;
#pragma unroll
        for (int off = 16; off; off >>= 1) mx = fmaxf(mx, __shfl_xor_sync(0xffffffffu, mx, off));
        float e = expf(sc - mx);
        float ssum = e;
#pragma unroll
        for (int off = 16; off; off >>= 1) ssum += __shfl_xor_sync(0xffffffffu, ssum, off);
        s_p[h * Kk + k] = e / ssum;
    }
    __syncthreads();

    // x[d] = sum_k p[d%4][k] * v[k][d]  (4-way k-split partials)
    {
        float acc = 0.f;
#pragma unroll
        for (int j = 0; j < 8; j++) {
            int k = part * 8 + j;
            acc += s_p[(d & 3) * Kk + k] * s_vv[k * 33 + d];
        }
        s_xp[part * Ddim + d] = acc;
    }
    __syncthreads();
    if (tid < Ddim)
        s_xp[tid] = s_xp[tid] + s_xp[Ddim + tid] + s_xp[2 * Ddim + tid] + s_xp[3 * Ddim + tid];
    __syncthreads();

    if (tid < Ddim) {
        float acc = bm[tid];
#pragma unroll
        for (int i = 0; i < Ddim; i++) acc += wm[tid * Ddim + i] * s_xp[i];
        s_cat[64 + tid] = acc;
        g_attn[((size_t)b * 32 + tid) * Mdim + m] = acc;
    }
    __syncthreads();

    if (tid < 64) {
        float acc = b1[tid];
#pragma unroll
        for (int i = 0; i < 96; i++) acc += w1[tid * 96 + i] * s_cat[i];
        g_h[((size_t)b * 64 + tid) * Mdim + m] = acc;
    }
}

// ===================== Kernel 3: instance-norm stats =====================
__global__ void k3_stats()
{
    const int bc = blockIdx.x;   // 0..127 = b*64+c
    const float* row = g_h + (size_t)bc * Mdim;
    float s = 0.f, s2 = 0.f;
    for (int i = threadIdx.x; i < Mdim; i += blockDim.x) {
        float v = row[i]; s += v; s2 += v * v;
    }
    __shared__ float rs[32], rs2[32];
#pragma unroll
    for (int off = 16; off; off >>= 1) {
        s  += __shfl_xor_sync(0xffffffffu, s, off);
        s2 += __shfl_xor_sync(0xffffffffu, s2, off);
    }
    if ((threadIdx.x & 31) == 0) { rs[threadIdx.x >> 5] = s; rs2[threadIdx.x >> 5] = s2; }
    __syncthreads();
    if (threadIdx.x == 0) {
        float S = 0.f, S2 = 0.f;
        for (int i = 0; i < (int)(blockDim.x >> 5); i++) { S += rs[i]; S2 += rs2[i]; }
        float mu = S / (float)Mdim;
        float var = S2 / (float)Mdim - mu * mu;
        g_mean[bc] = mu;
        g_istd[bc] = rsqrtf(var + 1e-5f);
    }
}

// ===================== Kernel 4: norm + relu + w2/wres output =====================
__global__ void k4_out(const float* __restrict__ src, const float* __restrict__ finv,
                       const float* __restrict__ w2, const float* __restrict__ b2,
                       const float* __restrict__ wres, const float* __restrict__ bres,
                       float* __restrict__ out)
{
    const int m = blockIdx.x, b = blockIdx.y;
    const int tid = threadIdx.x;
    __shared__ float s_cat[96], s_hn[64];

    if (tid < 32)      s_cat[tid] = finv[((size_t)b * 32 + tid) * Mdim + m];
    else if (tid < 64) s_cat[tid] = src[((size_t)b * 32 + tid - 32) * Mdim + m];
    else if (tid < 96) s_cat[tid] = g_attn[((size_t)b * 32 + tid - 64) * Mdim + m];
    if (tid < 64) {
        int bc = b * 64 + tid;
        float v = (g_h[(size_t)bc * Mdim + m] - g_mean[bc]) * g_istd[bc];
        s_hn[tid] = fmaxf(v, 0.f);
    }
    __syncthreads();

    if (tid < 32) {
        float acc = b2[tid] + bres[tid];
#pragma unroll
        for (int c = 0; c < 64; c++) acc += w2[tid * 64 + c] * s_hn[c];
#pragma unroll
        for (int i = 0; i < 96; i++) acc += wres[tid * 96 + i] * s_cat[i];
        out[((size_t)b * 32 + tid) * Mdim + m] = acc;
    }
}

// ===================== Kernel 5: R_indicator =====================
__global__ void k5_rind(const float* __restrict__ seqv, const float* __restrict__ teqv,
                        const int* __restrict__ perms, float* __restrict__ out)
{
    const int m = blockIdx.x, b = blockIdx.y;
    const int tid = threadIdx.x;   // block 64
    __shared__ float s_tk[Ff * Gg], s_sr[Ff * Gg];
    __shared__ int   s_p[Gg * Gg];
    __shared__ int   s_nn;

    if (tid == 0) s_nn = g_knn[((size_t)b * Mdim + m) * Kk];
    __syncthreads();
    const int nn = s_nn;

    for (int i = tid; i < Ff * Gg; i += blockDim.x) {
        int f = i / Gg, g = i % Gg;
        s_tk[i] = teqv[(((size_t)b * Ff + f) * Ndim + nn) * Gg + g];
        s_sr[i] = seqv[(((size_t)b * Ff + f) * Mdim + m) * Gg + g];
    }
    for (int i = tid; i < Gg * Gg; i += blockDim.x) s_p[i] = perms[i];
    __syncthreads();

    if (tid < Gg) {
        float acc = 0.f;
        for (int g = 0; g < Gg; g++) {
            int pv = s_p[g * Gg + tid];
#pragma unroll
            for (int f = 0; f < Ff; f++)
                acc += s_sr[f * Gg + pv] * s_tk[f * Gg + g];
        }
        out[(size_t)Bsz * 32 * Mdim + ((size_t)b * Gg + tid) * Mdim + m] = acc;
    }
}

// ===================== launch =====================
extern "C" void kernel_launch(void* const* d_in, const int* in_sizes, int n_in,
                              void* d_out, int out_size)
{
    const float* src  = (const float*)d_in[0];
    const float* tgt  = (const float*)d_in[1];
    const float* seqv = (const float*)d_in[2];
    const float* teqv = (const float*)d_in[3];
    const float* finv = (const float*)d_in[4];
    const int*   perms = (const int*)d_in[5];
    const float* wq = (const float*)d_in[6];   const float* bq = (const float*)d_in[7];
    const float* wk = (const float*)d_in[8];   const float* bk = (const float*)d_in[9];
    const float* wv = (const float*)d_in[10];  const float* bv = (const float*)d_in[11];
    const float* wm = (const float*)d_in[12];  const float* bm = (const float*)d_in[13];
    const float* w1 = (const float*)d_in[14];  const float* b1 = (const float*)d_in[15];
    const float* w2 = (const float*)d_in[16];  const float* b2 = (const float*)d_in[17];
    const float* wres = (const float*)d_in[18]; const float* bres = (const float*)d_in[19];
    float* out = (float*)d_out;

    const size_t smem1 = (size_t)(TM * Ndim + Ddim * TN) * sizeof(float);  // 80 KB
    cudaFuncSetAttribute(k1_score_topk, cudaFuncAttributeMaxDynamicSharedMemorySize, (int)smem1);

    k1_score_topk<<<dim3(Mdim / TM, Bsz), 256, smem1>>>(src, tgt);
    k2_attention<<<dim3(Mdim, Bsz), 128>>>(src, tgt, finv, wq, bq, wk, bk, wv, bv, wm, bm, w1, b1);
    k3_stats<<<128, 256>>>();
    k4_out<<<dim3(Mdim, Bsz), 128>>>(src, finv, w2, b2, wres, bres, out);
    k5_rind<<<dim3(Mdim, Bsz), 64>>>(seqv, teqv, perms, out);
}

// round 2
// speedup vs baseline: 1.0005x; 1.0005x over previous
#include <cuda_runtime.h>
#include <math.h>
#include <float.h>

#define Bsz 2
#define Mdim 2048
#define Ndim 2048
#define Ddim 32
#define Kk 32
#define Hh 4
#define DHh 8
#define Ff 8
#define Gg 60

// ---- scratch (no allocations allowed) ----
__device__ int   g_knn[Bsz * Mdim * Kk];
__device__ float g_h[Bsz * 64 * Mdim];
__device__ float g_attn[Bsz * 32 * Mdim];
__device__ float g_mean[Bsz * 64];
__device__ float g_istd[Bsz * 64];

// ===================== Kernel 1: score GEMM + top-K =====================
#define TM 8
#define TN 128
__global__ void k1_score_topk(const float* __restrict__ src, const float* __restrict__ tgt)
{
    extern __shared__ float sm[];
    float* s_scores = sm;               // TM * Ndim
    float* s_tile   = sm + TM * Ndim;   // Ddim * TN

    const int b    = blockIdx.y;
    const int m0   = blockIdx.x * TM;
    const int w    = threadIdx.x >> 5;
    const int lane = threadIdx.x & 31;
    const int m    = m0 + w;

    // source row for this warp's m (broadcast loads)
    float rsrc[Ddim];
#pragma unroll
    for (int d = 0; d < Ddim; d++)
        rsrc[d] = src[((size_t)b * Ddim + d) * Mdim + m];

    for (int t = 0; t < Ndim / TN; t++) {
        const int n0 = t * TN;
        for (int i = threadIdx.x; i < Ddim * TN; i += blockDim.x) {
            int d = i / TN, nn = i % TN;
            s_tile[i] = tgt[((size_t)b * Ddim + d) * Ndim + n0 + nn];
        }
        __syncthreads();

        float4 acc = make_float4(0.f, 0.f, 0.f, 0.f);
        const float4* tile4 = (const float4*)s_tile;
#pragma unroll
        for (int d = 0; d < Ddim; d++) {
            float4 tv = tile4[d * (TN / 4) + lane];
            acc.x += rsrc[d] * tv.x; acc.y += rsrc[d] * tv.y;
            acc.z += rsrc[d] * tv.z; acc.w += rsrc[d] * tv.w;
        }
        ((float4*)(s_scores + w * Ndim + n0))[lane] = acc;
        __syncthreads();
    }

    // top-K: iterative warp argmax over warp-private smem row.
    // Lane scans strided segment (idx % 32 == lane) -> conflict-free LDS.
    // Tie-break: smaller index wins (matches stable jax.lax.top_k).
    float* ws = s_scores + w * Ndim;
    for (int it = 0; it < Kk; it++) {
        float best = -FLT_MAX;
        int   bidx = 0x7fffffff;
        for (int j = 0; j < Ndim / 32; j++) {
            int idx = j * 32 + lane;
            float v = ws[idx];
            if (v > best) { best = v; bidx = idx; }
        }
#pragma unroll
        for (int off = 16; off; off >>= 1) {
            float ov = __shfl_down_sync(0xffffffffu, best, off);
            int   oi = __shfl_down_sync(0xffffffffu, bidx, off);
            if (ov > best || (ov == best && oi < bidx)) { best = ov; bidx = oi; }
        }
        bidx = __shfl_sync(0xffffffffu, bidx, 0);
        if ((bidx & 31) == lane) ws[bidx] = -FLT_MAX;
        if (lane == 0) g_knn[((size_t)b * Mdim + m) * Kk + it] = bidx;
        __syncwarp();
    }
}

// ===================== Kernel 2: kNN attention + MLP stage 1 =====================
__global__ void k2_attention(const float* __restrict__ src, const float* __restrict__ tgt,
                             const float* __restrict__ finv,
                             const float* __restrict__ wq, const float* __restrict__ bq,
                             const float* __restrict__ wk, const float* __restrict__ bk,
                             const float* __restrict__ wv, const float* __restrict__ bv,
                             const float* __restrict__ wm, const float* __restrict__ bm,
                             const float* __restrict__ w1, const float* __restrict__ b1)
{
    const int m = blockIdx.x, b = blockIdx.y;
    const int tid = threadIdx.x;

    __shared__ float s_feat[Kk * Ddim];       // [k][d], stride 32 (broadcast reads)
    __shared__ float s_kv[Kk * 33];           // [k][d], pad 33 (strided head reads)
    __shared__ float s_vv[Kk * 33];
    __shared__ float s_q[Ddim];
    __shared__ float s_p[Hh * Kk];
    __shared__ float s_xp[4 * Ddim];
    __shared__ float s_cat[96];
    __shared__ int   s_idx[Kk];

    if (tid < Kk) s_idx[tid] = g_knn[((size_t)b * Mdim + m) * Kk + tid];
    if (tid < 32) s_cat[32 + tid] = src[((size_t)b * Ddim + tid) * Mdim + m];
    if (tid >= 32 && tid < 64) s_cat[tid - 32] = finv[((size_t)b * Ddim + (tid - 32)) * Mdim + m];
    __syncthreads();

    for (int i = tid; i < Kk * Ddim; i += blockDim.x) {
        int k = i >> 5, d = i & 31;
        s_feat[k * Ddim + d] = tgt[((size_t)b * Ddim + d) * Ndim + s_idx[k]];
    }
    __syncthreads();

    const int d = tid & 31;
    const int part = tid >> 5;   // 0..3 (== warp id)

    if (part == 0) {
        float acc = bq[d];
#pragma unroll
        for (int i = 0; i < Ddim; i++) acc += wq[d * Ddim + i] * s_cat[32 + i];
        s_q[d] = acc;
    }
    {
        float wrow[Ddim];
#pragma unroll
        for (int i = 0; i < Ddim; i++) wrow[i] = wk[d * Ddim + i];
        float bias = bk[d];
#pragma unroll
        for (int j = 0; j < 8; j++) {
            int k = part * 8 + j;
            float acc = bias;
#pragma unroll
            for (int i = 0; i < Ddim; i++) acc += wrow[i] * s_feat[k * Ddim + i];
            s_kv[k * 33 + d] = acc;
        }
#pragma unroll
        for (int i = 0; i < Ddim; i++) wrow[i] = wv[d * Ddim + i];
        bias = bv[d];
#pragma unroll
        for (int j = 0; j < 8; j++) {
            int k = part * 8 + j;
            float acc = bias;
#pragma unroll
            for (int i = 0; i < Ddim; i++) acc += wrow[i] * s_feat[k * Ddim + i];
            s_vv[k * 33 + d] = acc;
        }
    }
    __syncthreads();

    // scores + softmax: warp h owns head h, lane = k
    {
        const int h = part;
        const int k = d;
        float sc = 0.f;
#pragma unroll
        for (int dh = 0; dh < DHh; dh++)
            sc += s_q[dh * Hh + h] * s_kv[k * 33 + dh * Hh + h];
        sc *= 0.3535533905932738f;   // 1/sqrt(8)
        float mx = sc;
#pragma unroll
        for (int off = 16; off; off >>= 1) mx = fmaxf(mx, __shfl_xor_sync(0xffffffffu, mx, off));
        float e = expf(sc - mx);
        float ssum = e;
#pragma unroll
        for (int off = 16; off; off >>= 1) ssum += __shfl_xor_sync(0xffffffffu, ssum, off);
        s_p[h * Kk + k] = e / ssum;
    }
    __syncthreads();

    // x[d] = sum_k p[d%4][k] * v[k][d]  (4-way k-split partials)
    {
        float acc = 0.f;
#pragma unroll
        for (int j = 0; j < 8; j++) {
            int k = part * 8 + j;
            acc += s_p[(d & 3) * Kk + k] * s_vv[k * 33 + d];
        }
        s_xp[part * Ddim + d] = acc;
    }
    __syncthreads();
    if (tid < Ddim)
        s_xp[tid] = s_xp[tid] + s_xp[Ddim + tid] + s_xp[2 * Ddim + tid] + s_xp[3 * Ddim + tid];
    __syncthreads();

    if (tid < Ddim) {
        float acc = bm[tid];
#pragma unroll
        for (int i = 0; i < Ddim; i++) acc += wm[tid * Ddim + i] * s_xp[i];
        s_cat[64 + tid] = acc;
        g_attn[((size_t)b * 32 + tid) * Mdim + m] = acc;
    }
    __syncthreads();

    if (tid < 64) {
        float acc = b1[tid];
#pragma unroll
        for (int i = 0; i < 96; i++) acc += w1[tid * 96 + i] * s_cat[i];
        g_h[((size_t)b * 64 + tid) * Mdim + m] = acc;
    }
}

// ===================== Kernel 3: instance-norm stats =====================
__global__ void k3_stats()
{
    const int bc = blockIdx.x;   // 0..127 = b*64+c
    const float* row = g_h + (size_t)bc * Mdim;
    float s = 0.f, s2 = 0.f;
    for (int i = threadIdx.x; i < Mdim; i += blockDim.x) {
        float v = row[i]; s += v; s2 += v * v;
    }
    __shared__ float rs[32], rs2[32];
#pragma unroll
    for (int off = 16; off; off >>= 1) {
        s  += __shfl_xor_sync(0xffffffffu, s, off);
        s2 += __shfl_xor_sync(0xffffffffu, s2, off);
    }
    if ((threadIdx.x & 31) == 0) { rs[threadIdx.x >> 5] = s; rs2[threadIdx.x >> 5] = s2; }
    __syncthreads();
    if (threadIdx.x == 0) {
        float S = 0.f, S2 = 0.f;
        for (int i = 0; i < (int)(blockDim.x >> 5); i++) { S += rs[i]; S2 += rs2[i]; }
        float mu = S / (float)Mdim;
        float var = S2 / (float)Mdim - mu * mu;
        g_mean[bc] = mu;
        g_istd[bc] = rsqrtf(var + 1e-5f);
    }
}

// ===================== Kernel 4: norm + relu + w2/wres output =====================
__global__ void k4_out(const float* __restrict__ src, const float* __restrict__ finv,
                       const float* __restrict__ w2, const float* __restrict__ b2,
                       const float* __restrict__ wres, const float* __restrict__ bres,
                       float* __restrict__ out)
{
    const int m = blockIdx.x, b = blockIdx.y;
    const int tid = threadIdx.x;
    __shared__ float s_cat[96], s_hn[64];

    if (tid < 32)      s_cat[tid] = finv[((size_t)b * 32 + tid) * Mdim + m];
    else if (tid < 64) s_cat[tid] = src[((size_t)b * 32 + tid - 32) * Mdim + m];
    else if (tid < 96) s_cat[tid] = g_attn[((size_t)b * 32 + tid - 64) * Mdim + m];
    if (tid < 64) {
        int bc = b * 64 + tid;
        float v = (g_h[(size_t)bc * Mdim + m] - g_mean[bc]) * g_istd[bc];
        s_hn[tid] = fmaxf(v, 0.f);
    }
    __syncthreads();

    if (tid < 32) {
        float acc = b2[tid] + bres[tid];
#pragma unroll
        for (int c = 0; c < 64; c++) acc += w2[tid * 64 + c] * s_hn[c];
#pragma unroll
        for (int i = 0; i < 96; i++) acc += wres[tid * 96 + i] * s_cat[i];
        out[((size_t)b * 32 + tid) * Mdim + m] = acc;
    }
}

// ===================== Kernel 5: R_indicator =====================
__global__ void k5_rind(const float* __restrict__ seqv, const float* __restrict__ teqv,
                        const int* __restrict__ perms, float* __restrict__ out)
{
    const int m = blockIdx.x, b = blockIdx.y;
    const int tid = threadIdx.x;   // block 64
    __shared__ float s_tk[Ff * Gg], s_sr[Ff * Gg];
    __shared__ int   s_p[Gg * Gg];
    __shared__ int   s_nn;

    if (tid == 0) s_nn = g_knn[((size_t)b * Mdim + m) * Kk];
    __syncthreads();
    const int nn = s_nn;

    for (int i = tid; i < Ff * Gg; i += blockDim.x) {
        int f = i / Gg, g = i % Gg;
        s_tk[i] = teqv[(((size_t)b * Ff + f) * Ndim + nn) * Gg + g];
        s_sr[i] = seqv[(((size_t)b * Ff + f) * Mdim + m) * Gg + g];
    }
    for (int i = tid; i < Gg * Gg; i += blockDim.x) s_p[i] = perms[i];
    __syncthreads();

    if (tid < Gg) {
        float acc = 0.f;
        for (int g = 0; g < Gg; g++) {
            int pv = s_p[g * Gg + tid];
#pragma unroll
            for (int f = 0; f < Ff; f++)
                acc += s_sr[f * Gg + pv] * s_tk[f * Gg + g];
        }
        out[(size_t)Bsz * 32 * Mdim + ((size_t)b * Gg + tid) * Mdim + m] = acc;
    }
}

// ===================== launch =====================
extern "C" void kernel_launch(void* const* d_in, const int* in_sizes, int n_in,
                              void* d_out, int out_size)
{
    const float* src  = (const float*)d_in[0];
    const float* tgt  = (const float*)d_in[1];
    const float* seqv = (const float*)d_in[2];
    const float* teqv = (const float*)d_in[3];
    const float* finv = (const float*)d_in[4];
    const int*   perms = (const int*)d_in[5];
    const float* wq = (const float*)d_in[6];   const float* bq = (const float*)d_in[7];
    const float* wk = (const float*)d_in[8];   const float* bk = (const float*)d_in[9];
    const float* wv = (const float*)d_in[10];  const float* bv = (const float*)d_in[11];
    const float* wm = (const float*)d_in[12];  const float* bm = (const float*)d_in[13];
    const float* w1 = (const float*)d_in[14];  const float* b1 = (const float*)d_in[15];
    const float* w2 = (const float*)d_in[16];  const float* b2 = (const float*)d_in[17];
    const float* wres = (const float*)d_in[18]; const float* bres = (const float*)d_in[19];
    float* out = (float*)d_out;

    const size_t smem1 = (size_t)(TM * Ndim + Ddim * TN) * sizeof(float);  // 80 KB
    cudaFuncSetAttribute(k1_score_topk, cudaFuncAttributeMaxDynamicSharedMemorySize, (int)smem1);

    k1_score_topk<<<dim3(Mdim / TM, Bsz), 256, smem1>>>(src, tgt);
    k2_attention<<<dim3(Mdim, Bsz), 128>>>(src, tgt, finv, wq, bq, wk, bk, wv, bv, wm, bm, w1, b1);
    k3_stats<<<128, 256>>>();
    k4_out<<<dim3(Mdim, Bsz), 128>>>(src, finv, w2, b2, wres, bres, out);
    k5_rind<<<dim3(Mdim, Bsz), 64>>>(seqv, teqv, perms, out);
}

// round 3
// speedup vs baseline: 2.7677x; 2.7662x over previous
#include <cuda_runtime.h>
#include <math.h>
#include <float.h>

#define Bsz 2
#define Mdim 2048
#define Ndim 2048
#define Kk 32
#define Gg 60
#define TM 16
#define TN 128

__device__ int   g_knn[Bsz * Mdim * Kk];
__device__ float g_qs[Bsz * Mdim * 32];
__device__ float g_kt[Bsz * Ndim * 32];
__device__ float g_vt[Bsz * Ndim * 32];
__device__ float g_x [Bsz * Mdim * 32];
__device__ float g_attn[Bsz * 32 * Mdim];
__device__ float g_h[Bsz * 64 * Mdim];
__device__ float g_mean[Bsz * 64];
__device__ float g_istd[Bsz * 64];

__device__ __forceinline__ unsigned ordf(float f) {
    unsigned u = __float_as_uint(f);
    return (u & 0x80000000u) ? ~u : (u | 0x80000000u);
}
__device__ __forceinline__ void ins4(float v, int n, float tv[4], int ti[4]) {
    if (v > tv[3]) {
        if (v > tv[1]) {
            if (v > tv[0]) { tv[3]=tv[2];ti[3]=ti[2]; tv[2]=tv[1];ti[2]=ti[1]; tv[1]=tv[0];ti[1]=ti[0]; tv[0]=v;ti[0]=n; }
            else           { tv[3]=tv[2];ti[3]=ti[2]; tv[2]=tv[1];ti[2]=ti[1]; tv[1]=v;ti[1]=n; }
        } else if (v > tv[2]) { tv[3]=tv[2];ti[3]=ti[2]; tv[2]=v;ti[2]=n; }
        else { tv[3]=v; ti[3]=n; }
    }
}

// ========== k0: per-point projections ==========
__global__ __launch_bounds__(256) void k0_proj(const float* __restrict__ in,
    const float* __restrict__ W1, const float* __restrict__ B1,
    const float* __restrict__ W2, const float* __restrict__ B2, int dual)
{
    __shared__ float sw1[1024], sw2[1024], sb1[32], sb2[32];
    const int tid = threadIdx.x;
    for (int i = tid; i < 1024; i += 256) { sw1[i] = W1[i]; if (dual) sw2[i] = W2[i]; }
    if (tid < 32) { sb1[tid] = B1[tid]; if (dual) sb2[tid] = B2[tid]; }
    __syncthreads();
    const int half = tid >> 7;
    const int p = blockIdx.x * 128 + (tid & 127);
    const int b = p >> 11, pl = p & 2047;
    float* o1 = dual ? g_kt : g_qs;
    float a1[16], a2[16];
#pragma unroll
    for (int o = 0; o < 16; o++) { a1[o] = sb1[half*16+o]; a2[o] = dual ? sb2[half*16+o] : 0.f; }
#pragma unroll
    for (int i = 0; i < 32; i++) {
        float xv = in[((size_t)(b*32+i))*2048 + pl];
#pragma unroll
        for (int o = 0; o < 16; o++) {
            a1[o] += sw1[(half*16+o)*32+i] * xv;
            if (dual) a2[o] += sw2[(half*16+o)*32+i] * xv;
        }
    }
#pragma unroll
    for (int o = 0; o < 16; o++) {
        o1[(size_t)p*32 + half*16+o] = a1[o];
        if (dual) g_vt[(size_t)p*32 + half*16+o] = a2[o];
    }
}

// ========== k1: score GEMM + top-K ==========
__device__ __forceinline__ void sel_topk(float* ws, float4* ws4, int lane,
                                         float tv[4], int ti[4], int* knnrow)
{
    int nvalid = 4;
    for (int it = 0; it < Kk; it++) {
        unsigned bu = __reduce_max_sync(0xffffffffu, ordf(tv[0]));
        int cand = (ordf(tv[0]) == bu) ? ti[0] : 0x7fffffff;
        int bi = __reduce_min_sync(0xffffffffu, cand);
        if (lane == 0) knnrow[it] = bi;
        if (ti[0] == bi) {
            ws[bi] = -FLT_MAX;
            tv[0]=tv[1];ti[0]=ti[1]; tv[1]=tv[2];ti[1]=ti[2]; tv[2]=tv[3];ti[2]=ti[3];
            tv[3] = -FLT_MAX; ti[3] = 0x7fffffff;
            if (--nvalid == 0) {
#pragma unroll 4
                for (int t = 0; t < Ndim/TN; t++) {
                    float4 v4 = ws4[t*32 + lane];
                    int nb = t*TN + lane*4;
                    ins4(v4.x,nb,tv,ti); ins4(v4.y,nb+1,tv,ti);
                    ins4(v4.z,nb+2,tv,ti); ins4(v4.w,nb+3,tv,ti);
                }
                nvalid = 4;
            }
        }
    }
}

__global__ __launch_bounds__(256, 1) void k1_score_topk(const float* __restrict__ src,
                                                        const float* __restrict__ tgt)
{
    extern __shared__ float sm[];
    float* s_scores = sm;                 // TM * Ndim
    float* s_tile   = sm + TM * Ndim;     // 32 * TN
    const int b = blockIdx.y, w = threadIdx.x >> 5, lane = threadIdx.x & 31;
    const int mA = blockIdx.x * TM + w * 2, mB = mA + 1;

    float rA[32], rB[32];
#pragma unroll
    for (int d = 0; d < 32; d++) {
        rA[d] = src[((size_t)(b*32+d))*Mdim + mA];
        rB[d] = src[((size_t)(b*32+d))*Mdim + mB];
    }
    float tvA[4] = {-FLT_MAX,-FLT_MAX,-FLT_MAX,-FLT_MAX};
    float tvB[4] = {-FLT_MAX,-FLT_MAX,-FLT_MAX,-FLT_MAX};
    int tiA[4] = {0x7fffffff,0x7fffffff,0x7fffffff,0x7fffffff};
    int tiB[4] = {0x7fffffff,0x7fffffff,0x7fffffff,0x7fffffff};

    float* wsA = s_scores + (w*2) * Ndim;
    float* wsB = wsA + Ndim;
    float4* wsA4 = (float4*)wsA;
    float4* wsB4 = (float4*)wsB;
    const float4* gt = (const float4*)(tgt + ((size_t)b*32)*Ndim);

    for (int t = 0; t < Ndim/TN; t++) {
        const int n0 = t * TN;
#pragma unroll
        for (int k = 0; k < 4; k++) {
            int i = threadIdx.x + k*256;             // 1024 float4 slots
            int d = i >> 5, c = i & 31;
            ((float4*)s_tile)[i] = gt[(size_t)d*(Ndim/4) + (n0>>2) + c];
        }
        __syncthreads();
        float4 aA = make_float4(0,0,0,0), aB = make_float4(0,0,0,0);
        const float4* tile4 = (const float4*)s_tile;
#pragma unroll
        for (int d = 0; d < 32; d++) {
            float4 tvv = tile4[d*32 + lane];
            aA.x += rA[d]*tvv.x; aA.y += rA[d]*tvv.y; aA.z += rA[d]*tvv.z; aA.w += rA[d]*tvv.w;
            aB.x += rB[d]*tvv.x; aB.y += rB[d]*tvv.y; aB.z += rB[d]*tvv.z; aB.w += rB[d]*tvv.w;
        }
        wsA4[t*32+lane] = aA; wsB4[t*32+lane] = aB;
        const int nb = n0 + lane*4;
        ins4(aA.x,nb,tvA,tiA); ins4(aA.y,nb+1,tvA,tiA); ins4(aA.z,nb+2,tvA,tiA); ins4(aA.w,nb+3,tvA,tiA);
        ins4(aB.x,nb,tvB,tiB); ins4(aB.y,nb+1,tvB,tiB); ins4(aB.z,nb+2,tvB,tiB); ins4(aB.w,nb+3,tvB,tiB);
        __syncthreads();
    }
    sel_topk(wsA, wsA4, lane, tvA, tiA, g_knn + ((size_t)b*Mdim + mA)*Kk);
    sel_topk(wsB, wsB4, lane, tvB, tiB, g_knn + ((size_t)b*Mdim + mB)*Kk);
}

// ========== k2: attention (warp per point) ==========
__global__ __launch_bounds__(256) void k2_attn()
{
    const int b = blockIdx.y, w = threadIdx.x >> 5, lane = threadIdx.x & 31;
    const int m = blockIdx.x * 8 + w;
    const size_t bm = (size_t)b * Mdim + m;
    const int nbr = g_knn[bm*Kk + lane];

    const float4* q4  = (const float4*)(g_qs + bm*32);
    const float4* kk4 = (const float4*)(g_kt + ((size_t)b*Ndim + nbr)*32);
    float s0=0,s1=0,s2=0,s3=0;
#pragma unroll
    for (int c = 0; c < 8; c++) {
        float4 qv = q4[c], kv = kk4[c];
        s0 += qv.x*kv.x; s1 += qv.y*kv.y; s2 += qv.z*kv.z; s3 += qv.w*kv.w;
    }
    const float sf = 0.35355339059327373f;
    s0*=sf; s1*=sf; s2*=sf; s3*=sf;
    float m0=s0,m1=s1,m2=s2,m3=s3;
#pragma unroll
    for (int o = 16; o; o >>= 1) {
        m0=fmaxf(m0,__shfl_xor_sync(0xffffffffu,m0,o));
        m1=fmaxf(m1,__shfl_xor_sync(0xffffffffu,m1,o));
        m2=fmaxf(m2,__shfl_xor_sync(0xffffffffu,m2,o));
        m3=fmaxf(m3,__shfl_xor_sync(0xffffffffu,m3,o));
    }
    float e0=expf(s0-m0), e1=expf(s1-m1), e2=expf(s2-m2), e3=expf(s3-m3);
    float z0=e0,z1=e1,z2=e2,z3=e3;
#pragma unroll
    for (int o = 16; o; o >>= 1) {
        z0+=__shfl_xor_sync(0xffffffffu,z0,o); z1+=__shfl_xor_sync(0xffffffffu,z1,o);
        z2+=__shfl_xor_sync(0xffffffffu,z2,o); z3+=__shfl_xor_sync(0xffffffffu,z3,o);
    }
    const float p0=e0/z0, p1=e1/z1, p2=e2/z2, p3=e3/z3;

    const float4* vv4 = (const float4*)(g_vt + ((size_t)b*Ndim + nbr)*32);
    float xc[32];
#pragma unroll
    for (int c = 0; c < 8; c++) {
        float4 vv = vv4[c];
        xc[4*c+0]=p0*vv.x; xc[4*c+1]=p1*vv.y; xc[4*c+2]=p2*vv.z; xc[4*c+3]=p3*vv.w;
    }
#pragma unroll
    for (int o = 16; o; o >>= 1)
#pragma unroll
        for (int d = 0; d < 32; d++) xc[d] += __shfl_xor_sync(0xffffffffu, xc[d], o);
    float xo = 0.f;
#pragma unroll
    for (int d = 0; d < 32; d++) if (lane == d) xo = xc[d];
    g_x[bm*32 + lane] = xo;
}

// ========== k2b: wm + w1 (GEMM over m) ==========
__global__ __launch_bounds__(128) void k2b_mlp(const float* __restrict__ finv, const float* __restrict__ srcf,
    const float* __restrict__ wm, const float* __restrict__ bm_,
    const float* __restrict__ w1, const float* __restrict__ b1_)
{
    __shared__ float s_wm[1024], s_w1[6144], s_bm[32], s_b1[64];
    __shared__ float s_x[32*33], s_attn[32*33];
    const int b = blockIdx.y, tid = threadIdx.x, m0 = blockIdx.x * 32;
    const int lane = tid & 31, og = tid >> 5, m = m0 + lane;

    for (int i = tid; i < 6144; i += 128) s_w1[i] = w1[i];
    for (int i = tid; i < 1024; i += 128) s_wm[i] = wm[i];
    if (tid < 64) s_b1[tid] = b1_[tid];
    if (tid < 32) s_bm[tid] = bm_[tid];
    for (int i = tid; i < 1024; i += 128) {
        int ml = i >> 5, d = i & 31;
        s_x[ml*33+d] = g_x[(((size_t)b*Mdim + m0) << 5) + i];
    }
    __syncthreads();
    float a[8];
#pragma unroll
    for (int j = 0; j < 8; j++) a[j] = s_bm[og*8+j];
#pragma unroll
    for (int i = 0; i < 32; i++) {
        float xv = s_x[lane*33+i];
#pragma unroll
        for (int j = 0; j < 8; j++) a[j] += s_wm[(og*8+j)*32+i] * xv;
    }
#pragma unroll
    for (int j = 0; j < 8; j++) {
        int o = og*8+j;
        s_attn[lane*33+o] = a[j];
        g_attn[((size_t)(b*32+o))*Mdim + m] = a[j];
    }
    __syncthreads();
    float h[16];
#pragma unroll
    for (int j = 0; j < 16; j++) h[j] = s_b1[og*16+j];
#pragma unroll
    for (int i = 0; i < 32; i++) {
        float xv = finv[((size_t)(b*32+i))*Mdim + m];
#pragma unroll
        for (int j = 0; j < 16; j++) h[j] += s_w1[(og*16+j)*96+i] * xv;
    }
#pragma unroll
    for (int i = 0; i < 32; i++) {
        float xv = srcf[((size_t)(b*32+i))*Mdim + m];
#pragma unroll
        for (int j = 0; j < 16; j++) h[j] += s_w1[(og*16+j)*96+32+i] * xv;
    }
#pragma unroll
    for (int i = 0; i < 32; i++) {
        float xv = s_attn[lane*33+i];
#pragma unroll
        for (int j = 0; j < 16; j++) h[j] += s_w1[(og*16+j)*96+64+i] * xv;
    }
#pragma unroll
    for (int j = 0; j < 16; j++)
        g_h[((size_t)(b*64 + og*16+j))*Mdim + m] = h[j];
}

// ========== k3: instance-norm stats ==========
__global__ void k3_stats()
{
    const int bc = blockIdx.x;
    const float* row = g_h + (size_t)bc * Mdim;
    float s = 0.f, s2 = 0.f;
    for (int i = threadIdx.x; i < Mdim; i += blockDim.x) {
        float v = row[i]; s += v; s2 += v*v;
    }
    __shared__ float rs[32], rs2[32];
#pragma unroll
    for (int o = 16; o; o >>= 1) {
        s += __shfl_xor_sync(0xffffffffu, s, o);
        s2 += __shfl_xor_sync(0xffffffffu, s2, o);
    }
    if ((threadIdx.x & 31) == 0) { rs[threadIdx.x>>5] = s; rs2[threadIdx.x>>5] = s2; }
    __syncthreads();
    if (threadIdx.x == 0) {
        float S = 0, S2 = 0;
        for (int i = 0; i < (int)(blockDim.x>>5); i++) { S += rs[i]; S2 += rs2[i]; }
        float mu = S / (float)Mdim;
        float var = S2 / (float)Mdim - mu*mu;
        g_mean[bc] = mu; g_istd[bc] = rsqrtf(var + 1e-5f);
    }
}

// ========== k4: norm + relu + w2/wres (GEMM over m) ==========
__global__ __launch_bounds__(128) void k4_out(const float* __restrict__ finv, const float* __restrict__ srcf,
    const float* __restrict__ w2, const float* __restrict__ b2_,
    const float* __restrict__ wres, const float* __restrict__ bres, float* __restrict__ out)
{
    __shared__ float s_w[32*160], s_in[160*33], s_b[32];
    const int b = blockIdx.y, tid = threadIdx.x, m0 = blockIdx.x * 32;
    const int lane = tid & 31, og = tid >> 5;

    for (int i = tid; i < 5120; i += 128) {
        int o = i / 160, c = i % 160;
        s_w[i] = (c < 64) ? w2[o*64+c] : wres[o*96 + (c-64)];
    }
    if (tid < 32) s_b[tid] = b2_[tid] + bres[tid];
    for (int i = tid; i < 2048; i += 128) {
        int c = i >> 5, ml = i & 31;
        int bc = b*64 + c;
        float v = (g_h[(size_t)bc*Mdim + m0+ml] - g_mean[bc]) * g_istd[bc];
        s_in[c*33+ml] = fmaxf(v, 0.f);
    }
    for (int i = tid; i < 1024; i += 128) {
        int c = i >> 5, ml = i & 31;
        s_in[(64 +c)*33+ml] = finv[((size_t)(b*32+c))*Mdim + m0+ml];
        s_in[(96 +c)*33+ml] = srcf[((size_t)(b*32+c))*Mdim + m0+ml];
        s_in[(128+c)*33+ml] = g_attn[((size_t)(b*32+c))*Mdim + m0+ml];
    }
    __syncthreads();
    float acc[8];
#pragma unroll
    for (int j = 0; j < 8; j++) acc[j] = s_b[og*8+j];
    for (int c = 0; c < 160; c++) {
        float xv = s_in[c*33+lane];
#pragma unroll
        for (int j = 0; j < 8; j++) acc[j] += s_w[(og*8+j)*160+c] * xv;
    }
#pragma unroll
    for (int j = 0; j < 8; j++)
        out[((size_t)(b*32 + og*8+j))*Mdim + m0+lane] = acc[j];
}

// ========== k5: R_indicator ==========
__global__ __launch_bounds__(64) void k5_rind(const float* __restrict__ seqv, const float* __restrict__ teqv,
                                              const int* __restrict__ perms, float* __restrict__ out)
{
    __shared__ int   s_p[Gg*Gg];
    __shared__ float s_sr[Gg*8], s_tk[Gg*8];
    __shared__ int s_nn;
    const int b = blockIdx.y, tid = threadIdx.x;
    for (int i = tid; i < Gg*Gg; i += 64) s_p[i] = perms[i];

    for (int r = 0; r < 8; r++) {
        const int m = blockIdx.x * 8 + r;
        if (tid == 0) s_nn = g_knn[((size_t)b*Mdim + m)*Kk];
        __syncthreads();
        const int nn = s_nn;
        for (int i = tid; i < Gg*8; i += 64) {
            int f = i / Gg, j = i % Gg;
            s_sr[j*8+f] = seqv[(((size_t)(b*8+f))*Mdim + m )*Gg + j];
            s_tk[j*8+f] = teqv[(((size_t)(b*8+f))*Ndim + nn)*Gg + j];
        }
        __syncthreads();
        if (tid < Gg) {
            float acc = 0.f;
            const float4* sr4 = (const float4*)s_sr;
            const float4* tk4 = (const float4*)s_tk;
            for (int g = 0; g < Gg; g++) {
                int pv = s_p[g*Gg + tid];
                float4 a0 = sr4[pv*2], a1 = sr4[pv*2+1];
                float4 t0 = tk4[g*2],  t1 = tk4[g*2+1];
                acc += a0.x*t0.x + a0.y*t0.y + a0.z*t0.z + a0.w*t0.w
                     + a1.x*t1.x + a1.y*t1.y + a1.z*t1.z + a1.w*t1.w;
            }
            out[(size_t)Bsz*32*Mdim + ((size_t)b*Gg + tid)*Mdim + m] = acc;
        }
        __syncthreads();
    }
}

// ========== launch ==========
extern "C" void kernel_launch(void* const* d_in, const int* in_sizes, int n_in,
                              void* d_out, int out_size)
{
    (void)in_sizes; (void)n_in; (void)out_size;
    const float* src  = (const float*)d_in[0];
    const float* tgt  = (const float*)d_in[1];
    const float* seqv = (const float*)d_in[2];
    const float* teqv = (const float*)d_in[3];
    const float* finv = (const float*)d_in[4];
    const int*   perms = (const int*)d_in[5];
    const float* wq = (const float*)d_in[6];   const float* bq = (const float*)d_in[7];
    const float* wk = (const float*)d_in[8];   const float* bk = (const float*)d_in[9];
    const float* wv = (const float*)d_in[10];  const float* bv = (const float*)d_in[11];
    const float* wm = (const float*)d_in[12];  const float* bm = (const float*)d_in[13];
    const float* w1 = (const float*)d_in[14];  const float* b1 = (const float*)d_in[15];
    const float* w2 = (const float*)d_in[16];  const float* b2 = (const float*)d_in[17];
    const float* wres = (const float*)d_in[18]; const float* bres = (const float*)d_in[19];
    float* out = (float*)d_out;

    const int smem1 = (TM * Ndim + 32 * TN) * 4;   // 147456 B
    cudaFuncSetAttribute(k1_score_topk, cudaFuncAttributeMaxDynamicSharedMemorySize, smem1);

    k0_proj<<<32, 256>>>(src, wq, bq, wq, bq, 0);
    k0_proj<<<32, 256>>>(tgt, wk, bk, wv, bv, 1);
    k1_score_topk<<<dim3(Mdim/TM, Bsz), 256, smem1>>>(src, tgt);
    k2_attn<<<dim3(Mdim/8, Bsz), 256>>>();
    k2b_mlp<<<dim3(Mdim/32, Bsz), 128>>>(finv, src, wm, bm, w1, b1);
    k3_stats<<<128, 256>>>();
    k4_out<<<dim3(Mdim/32, Bsz), 128>>>(finv, src, w2, b2, wres, bres, out);
    k5_rind<<<dim3(Mdim/8, Bsz), 64>>>(seqv, teqv, perms, out);
}

// round 4
// speedup vs baseline: 3.3690x; 1.2173x over previous
#include <cuda_runtime.h>
#include <math.h>
#include <float.h>

#define Bsz 2
#define Mdim 2048
#define Ndim 2048
#define Kk 32
#define Gg 60
#define TMR 8          // rows per block in k1
#define TN 256         // n per tile in k1

__device__ int   g_nn[Bsz * Mdim];
__device__ float g_qs[Bsz * Mdim * 32];
__device__ float g_kt[Bsz * Ndim * 32];
__device__ float g_vt[Bsz * Ndim * 32];
__device__ float g_x [Bsz * Mdim * 32];
__device__ float g_attn[Bsz * 32 * Mdim];
__device__ float g_h[Bsz * 64 * Mdim];
__device__ float g_mean[Bsz * 64];
__device__ float g_istd[Bsz * 64];

__device__ __forceinline__ unsigned ordf(float f) {
    unsigned u = __float_as_uint(f);
    return (u & 0x80000000u) ? ~u : (u | 0x80000000u);
}
__device__ __forceinline__ void ins4(float v, int n, float tv[4], int ti[4]) {
    if (v > tv[3]) {
        if (v > tv[1]) {
            if (v > tv[0]) { tv[3]=tv[2];ti[3]=ti[2]; tv[2]=tv[1];ti[2]=ti[1]; tv[1]=tv[0];ti[1]=ti[0]; tv[0]=v;ti[0]=n; }
            else           { tv[3]=tv[2];ti[3]=ti[2]; tv[2]=tv[1];ti[2]=ti[1]; tv[1]=v;ti[1]=n; }
        } else if (v > tv[2]) { tv[3]=tv[2];ti[3]=ti[2]; tv[2]=v;ti[2]=n; }
        else { tv[3]=v; ti[3]=n; }
    }
}

// ========== k0: per-point projections (z=0: Q from src; z=1: K,V from tgt) ==========
__global__ __launch_bounds__(256) void k0_proj(const float* __restrict__ src, const float* __restrict__ tgt,
    const float* __restrict__ wq, const float* __restrict__ bq,
    const float* __restrict__ wk, const float* __restrict__ bk,
    const float* __restrict__ wv, const float* __restrict__ bv)
{
    __shared__ float sw1[1024], sw2[1024], sb1[32], sb2[32];
    const int tid = threadIdx.x;
    const int dual = blockIdx.z;
    const float* in = dual ? tgt : src;
    const float* W1 = dual ? wk : wq;  const float* B1 = dual ? bk : bq;
    for (int i = tid; i < 1024; i += 256) { sw1[i] = W1[i]; if (dual) sw2[i] = wv[i]; }
    if (tid < 32) { sb1[tid] = B1[tid]; if (dual) sb2[tid] = bv[tid]; }
    __syncthreads();
    const int half = tid >> 7;
    const int p = blockIdx.x * 128 + (tid & 127);
    const int b = p >> 11, pl = p & 2047;
    float* o1 = dual ? g_kt : g_qs;
    float a1[16], a2[16];
#pragma unroll
    for (int o = 0; o < 16; o++) { a1[o] = sb1[half*16+o]; a2[o] = dual ? sb2[half*16+o] : 0.f; }
#pragma unroll
    for (int i = 0; i < 32; i++) {
        float xv = in[((size_t)(b*32+i))*2048 + pl];
#pragma unroll
        for (int o = 0; o < 16; o++) {
            a1[o] += sw1[(half*16+o)*32+i] * xv;
            if (dual) a2[o] += sw2[(half*16+o)*32+i] * xv;
        }
    }
#pragma unroll
    for (int o = 0; o < 16; o++) {
        o1[(size_t)p*32 + half*16+o] = a1[o];
        if (dual) g_vt[(size_t)p*32 + half*16+o] = a2[o];
    }
}

// ========== k1f: score GEMM + top-K + fused attention ==========
__global__ __launch_bounds__(256) void k1_fused(const float* __restrict__ src,
                                                const float* __restrict__ tgt)
{
    extern __shared__ float sm[];
    float* s_scores = sm;                   // TMR * 2048
    float* s_tile   = sm + TMR * Ndim;      // 32 * TN
    const int b = blockIdx.y, w = threadIdx.x >> 5, lane = threadIdx.x & 31;
    const int m = blockIdx.x * TMR + w;
    const size_t bm = (size_t)b * Mdim + m;
    const size_t bn = (size_t)b * Ndim;

    float rsrc[32];
#pragma unroll
    for (int d = 0; d < 32; d++)
        rsrc[d] = src[((size_t)(b*32+d))*Mdim + m];

    float tv[4] = {-FLT_MAX,-FLT_MAX,-FLT_MAX,-FLT_MAX};
    int   ti[4] = {0x7fffffff,0x7fffffff,0x7fffffff,0x7fffffff};

    float* ws = s_scores + w * Ndim;
    float4* ws4 = (float4*)ws;
    const float4* gt = (const float4*)(tgt + ((size_t)b*32)*Ndim);

    for (int t = 0; t < Ndim/TN; t++) {
        const int n0 = t * TN;
#pragma unroll
        for (int kk = 0; kk < 8; kk++) {
            int i = threadIdx.x + kk*256;        // 2048 float4 slots
            int d = i >> 6, c = i & 63;
            ((float4*)s_tile)[i] = gt[(size_t)d*(Ndim/4) + (n0>>2) + c];
        }
        __syncthreads();
        float4 a0 = make_float4(0,0,0,0), a1 = make_float4(0,0,0,0);
        const float4* tile4 = (const float4*)s_tile;
#pragma unroll
        for (int d = 0; d < 32; d++) {
            float r = rsrc[d];
            float4 t0 = tile4[d*64 + lane];
            float4 t1 = tile4[d*64 + 32 + lane];
            a0.x += r*t0.x; a0.y += r*t0.y; a0.z += r*t0.z; a0.w += r*t0.w;
            a1.x += r*t1.x; a1.y += r*t1.y; a1.z += r*t1.z; a1.w += r*t1.w;
        }
        ws4[t*64 + lane] = a0; ws4[t*64 + 32 + lane] = a1;
        const int nb0 = n0 + lane*4, nb1 = n0 + 128 + lane*4;
        ins4(a0.x,nb0,tv,ti); ins4(a0.y,nb0+1,tv,ti); ins4(a0.z,nb0+2,tv,ti); ins4(a0.w,nb0+3,tv,ti);
        ins4(a1.x,nb1,tv,ti); ins4(a1.y,nb1+1,tv,ti); ins4(a1.z,nb1+2,tv,ti); ins4(a1.w,nb1+3,tv,ti);
        __syncthreads();
    }

    // ---- selection: 32 iterations, lane `it` keeps neighbor #it ----
    int nvalid = 4;
    int nbr = 0;
    for (int it = 0; it < Kk; it++) {
        unsigned bu = __reduce_max_sync(0xffffffffu, ordf(tv[0]));
        int cand = (ordf(tv[0]) == bu) ? ti[0] : 0x7fffffff;
        int bi = __reduce_min_sync(0xffffffffu, cand);
        if (lane == it) nbr = bi;
        if (it == 0 && lane == 0) g_nn[bm] = bi;
        if (ti[0] == bi) {
            ws[bi] = -FLT_MAX;
            tv[0]=tv[1];ti[0]=ti[1]; tv[1]=tv[2];ti[1]=ti[2]; tv[2]=tv[3];ti[2]=ti[3];
            tv[3] = -FLT_MAX; ti[3] = 0x7fffffff;
            if (--nvalid == 0) {
#pragma unroll 4
                for (int t = 0; t < Ndim/TN; t++) {
                    float4 v0 = ws4[t*64 + lane];
                    float4 v1 = ws4[t*64 + 32 + lane];
                    int nb0 = t*TN + lane*4, nb1 = t*TN + 128 + lane*4;
                    ins4(v0.x,nb0,tv,ti); ins4(v0.y,nb0+1,tv,ti); ins4(v0.z,nb0+2,tv,ti); ins4(v0.w,nb0+3,tv,ti);
                    ins4(v1.x,nb1,tv,ti); ins4(v1.y,nb1+1,tv,ti); ins4(v1.z,nb1+2,tv,ti); ins4(v1.w,nb1+3,tv,ti);
                }
                nvalid = 4;
            }
        }
    }

    // ---- fused attention: lane = k-index, neighbor = nbr ----
    const float4* q4  = (const float4*)(g_qs + bm*32);
    const float4* kk4 = (const float4*)(g_kt + (bn + nbr)*32);
    float s0=0,s1=0,s2=0,s3=0;
#pragma unroll
    for (int c = 0; c < 8; c++) {
        float4 qv = q4[c], kv = kk4[c];
        s0 += qv.x*kv.x; s1 += qv.y*kv.y; s2 += qv.z*kv.z; s3 += qv.w*kv.w;
    }
    const float sf = 0.35355339059327373f;   // 1/sqrt(8)
    s0*=sf; s1*=sf; s2*=sf; s3*=sf;
    float m0=s0,m1=s1,m2=s2,m3=s3;
#pragma unroll
    for (int o = 16; o; o >>= 1) {
        m0=fmaxf(m0,__shfl_xor_sync(0xffffffffu,m0,o));
        m1=fmaxf(m1,__shfl_xor_sync(0xffffffffu,m1,o));
        m2=fmaxf(m2,__shfl_xor_sync(0xffffffffu,m2,o));
        m3=fmaxf(m3,__shfl_xor_sync(0xffffffffu,m3,o));
    }
    float e0=expf(s0-m0), e1=expf(s1-m1), e2=expf(s2-m2), e3=expf(s3-m3);
    float z0=e0,z1=e1,z2=e2,z3=e3;
#pragma unroll
    for (int o = 16; o; o >>= 1) {
        z0+=__shfl_xor_sync(0xffffffffu,z0,o); z1+=__shfl_xor_sync(0xffffffffu,z1,o);
        z2+=__shfl_xor_sync(0xffffffffu,z2,o); z3+=__shfl_xor_sync(0xffffffffu,z3,o);
    }
    const float p0=e0/z0, p1=e1/z1, p2=e2/z2, p3=e3/z3;

    // transposed V stage in (dead) score smem: sT[d][k] stride 33, sP[k][r]
    float* sT = ws;            // 32*33 = 1056 floats
    float* sP = ws + 1056;     // 128 floats
    const float4* vv4 = (const float4*)(g_vt + (bn + nbr)*32);
#pragma unroll
    for (int c = 0; c < 8; c++) {
        float4 vv = vv4[c];
        sT[(4*c+0)*33 + lane] = vv.x;
        sT[(4*c+1)*33 + lane] = vv.y;
        sT[(4*c+2)*33 + lane] = vv.z;
        sT[(4*c+3)*33 + lane] = vv.w;
    }
    ((float4*)sP)[lane] = make_float4(p0, p1, p2, p3);
    __syncwarp();
    float acc = 0.f;
    const int r = lane & 3;
#pragma unroll
    for (int k = 0; k < 32; k++)
        acc += sP[k*4 + r] * sT[lane*33 + k];
    g_x[bm*32 + lane] = acc;
}

// ========== k2b: wm + w1 (GEMM over m) ==========
__global__ __launch_bounds__(128) void k2b_mlp(const float* __restrict__ finv, const float* __restrict__ srcf,
    const float* __restrict__ wm, const float* __restrict__ bm_,
    const float* __restrict__ w1, const float* __restrict__ b1_)
{
    __shared__ float s_wm[1024], s_w1[6144], s_bm[32], s_b1[64];
    __shared__ float s_x[32*33], s_attn[32*33];
    const int b = blockIdx.y, tid = threadIdx.x, m0 = blockIdx.x * 32;
    const int lane = tid & 31, og = tid >> 5, m = m0 + lane;

    for (int i = tid; i < 6144; i += 128) s_w1[i] = w1[i];
    for (int i = tid; i < 1024; i += 128) s_wm[i] = wm[i];
    if (tid < 64) s_b1[tid] = b1_[tid];
    if (tid < 32) s_bm[tid] = bm_[tid];
    for (int i = tid; i < 1024; i += 128) {
        int ml = i >> 5, d = i & 31;
        s_x[ml*33+d] = g_x[(((size_t)b*Mdim + m0) << 5) + i];
    }
    __syncthreads();
    float a[8];
#pragma unroll
    for (int j = 0; j < 8; j++) a[j] = s_bm[og*8+j];
#pragma unroll
    for (int i = 0; i < 32; i++) {
        float xv = s_x[lane*33+i];
#pragma unroll
        for (int j = 0; j < 8; j++) a[j] += s_wm[(og*8+j)*32+i] * xv;
    }
#pragma unroll
    for (int j = 0; j < 8; j++) {
        int o = og*8+j;
        s_attn[lane*33+o] = a[j];
        g_attn[((size_t)(b*32+o))*Mdim + m] = a[j];
    }
    __syncthreads();
    float h[16];
#pragma unroll
    for (int j = 0; j < 16; j++) h[j] = s_b1[og*16+j];
#pragma unroll
    for (int i = 0; i < 32; i++) {
        float xv = finv[((size_t)(b*32+i))*Mdim + m];
#pragma unroll
        for (int j = 0; j < 16; j++) h[j] += s_w1[(og*16+j)*96+i] * xv;
    }
#pragma unroll
    for (int i = 0; i < 32; i++) {
        float xv = srcf[((size_t)(b*32+i))*Mdim + m];
#pragma unroll
        for (int j = 0; j < 16; j++) h[j] += s_w1[(og*16+j)*96+32+i] * xv;
    }
#pragma unroll
    for (int i = 0; i < 32; i++) {
        float xv = s_attn[lane*33+i];
#pragma unroll
        for (int j = 0; j < 16; j++) h[j] += s_w1[(og*16+j)*96+64+i] * xv;
    }
#pragma unroll
    for (int j = 0; j < 16; j++)
        g_h[((size_t)(b*64 + og*16+j))*Mdim + m] = h[j];
}

// ========== k3: instance-norm stats ==========
__global__ void k3_stats()
{
    const int bc = blockIdx.x;
    const float* row = g_h + (size_t)bc * Mdim;
    float s = 0.f, s2 = 0.f;
    for (int i = threadIdx.x; i < Mdim; i += blockDim.x) {
        float v = row[i]; s += v; s2 += v*v;
    }
    __shared__ float rs[32], rs2[32];
#pragma unroll
    for (int o = 16; o; o >>= 1) {
        s += __shfl_xor_sync(0xffffffffu, s, o);
        s2 += __shfl_xor_sync(0xffffffffu, s2, o);
    }
    if ((threadIdx.x & 31) == 0) { rs[threadIdx.x>>5] = s; rs2[threadIdx.x>>5] = s2; }
    __syncthreads();
    if (threadIdx.x == 0) {
        float S = 0, S2 = 0;
        for (int i = 0; i < (int)(blockDim.x>>5); i++) { S += rs[i]; S2 += rs2[i]; }
        float mu = S / (float)Mdim;
        float var = S2 / (float)Mdim - mu*mu;
        g_mean[bc] = mu; g_istd[bc] = rsqrtf(var + 1e-5f);
    }
}

// ========== k4: norm + relu + w2/wres (GEMM over m) ==========
__global__ __launch_bounds__(128) void k4_out(const float* __restrict__ finv, const float* __restrict__ srcf,
    const float* __restrict__ w2, const float* __restrict__ b2_,
    const float* __restrict__ wres, const float* __restrict__ bres, float* __restrict__ out)
{
    __shared__ float s_w[32*160], s_in[160*33], s_b[32];
    const int b = blockIdx.y, tid = threadIdx.x, m0 = blockIdx.x * 32;
    const int lane = tid & 31, og = tid >> 5;

    for (int i = tid; i < 5120; i += 128) {
        int o = i / 160, c = i % 160;
        s_w[i] = (c < 64) ? w2[o*64+c] : wres[o*96 + (c-64)];
    }
    if (tid < 32) s_b[tid] = b2_[tid] + bres[tid];
    for (int i = tid; i < 2048; i += 128) {
        int c = i >> 5, ml = i & 31;
        int bc = b*64 + c;
        float v = (g_h[(size_t)bc*Mdim + m0+ml] - g_mean[bc]) * g_istd[bc];
        s_in[c*33+ml] = fmaxf(v, 0.f);
    }
    for (int i = tid; i < 1024; i += 128) {
        int c = i >> 5, ml = i & 31;
        s_in[(64 +c)*33+ml] = finv[((size_t)(b*32+c))*Mdim + m0+ml];
        s_in[(96 +c)*33+ml] = srcf[((size_t)(b*32+c))*Mdim + m0+ml];
        s_in[(128+c)*33+ml] = g_attn[((size_t)(b*32+c))*Mdim + m0+ml];
    }
    __syncthreads();
    float acc[8];
#pragma unroll
    for (int j = 0; j < 8; j++) acc[j] = s_b[og*8+j];
    for (int c = 0; c < 160; c++) {
        float xv = s_in[c*33+lane];
#pragma unroll
        for (int j = 0; j < 8; j++) acc[j] += s_w[(og*8+j)*160+c] * xv;
    }
#pragma unroll
    for (int j = 0; j < 8; j++)
        out[((size_t)(b*32 + og*8+j))*Mdim + m0+lane] = acc[j];
}

// ========== k5: R_indicator via C-matrix ==========
__global__ __launch_bounds__(128) void k5_rind(const float* __restrict__ seqv, const float* __restrict__ teqv,
                                               const int* __restrict__ perms, float* __restrict__ out)
{
    __shared__ int   s_p[Gg*Gg];
    __shared__ float s_sr[Gg*8];      // [j][f]  stride 8 (broadcast reads)
    __shared__ float s_tk[Gg*12];     // [g][f]  stride 12 (pad: 4-way max conflict)
    __shared__ float s_C[Gg*Gg];      // [j][g]
    __shared__ int s_nn;
    const int b = blockIdx.y, tid = threadIdx.x;
    for (int i = tid; i < Gg*Gg; i += 128) s_p[i] = perms[i];

    for (int rr = 0; rr < 8; rr++) {
        const int m = blockIdx.x * 8 + rr;
        __syncthreads();
        if (tid == 0) s_nn = g_nn[(size_t)b*Mdim + m];
        __syncthreads();
        const int nn = s_nn;
        for (int i = tid; i < Gg*8; i += 128) {
            int f = i / Gg, j = i % Gg;
            s_sr[j*8  + f] = seqv[(((size_t)(b*8+f))*Mdim + m )*Gg + j];
            s_tk[j*12 + f] = teqv[(((size_t)(b*8+f))*Ndim + nn)*Gg + j];
        }
        __syncthreads();
        const float4* sr4 = (const float4*)s_sr;
        for (int idx = tid; idx < Gg*Gg; idx += 128) {
            int j = idx / Gg, g = idx % Gg;
            float4 a0 = sr4[j*2], a1 = sr4[j*2+1];
            const float4* tg = (const float4*)(s_tk + g*12);
            float4 t0 = tg[0], t1 = tg[1];
            s_C[j*Gg + g] = a0.x*t0.x + a0.y*t0.y + a0.z*t0.z + a0.w*t0.w
                          + a1.x*t1.x + a1.y*t1.y + a1.z*t1.z + a1.w*t1.w;
        }
        __syncthreads();
        if (tid < Gg) {
            float acc = 0.f;
#pragma unroll 4
            for (int g = 0; g < Gg; g++)
                acc += s_C[s_p[g*Gg + tid]*Gg + g];
            out[(size_t)Bsz*32*Mdim + ((size_t)b*Gg + tid)*Mdim + m] = acc;
        }
    }
}

// ========== launch ==========
extern "C" void kernel_launch(void* const* d_in, const int* in_sizes, int n_in,
                              void* d_out, int out_size)
{
    (void)in_sizes; (void)n_in; (void)out_size;
    const float* src  = (const float*)d_in[0];
    const float* tgt  = (const float*)d_in[1];
    const float* seqv = (const float*)d_in[2];
    const float* teqv = (const float*)d_in[3];
    const float* finv = (const float*)d_in[4];
    const int*   perms = (const int*)d_in[5];
    const float* wq = (const float*)d_in[6];   const float* bq = (const float*)d_in[7];
    const float* wk = (const float*)d_in[8];   const float* bk = (const float*)d_in[9];
    const float* wv = (const float*)d_in[10];  const float* bv = (const float*)d_in[11];
    const float* wm = (const float*)d_in[12];  const float* bm = (const float*)d_in[13];
    const float* w1 = (const float*)d_in[14];  const float* b1 = (const float*)d_in[15];
    const float* w2 = (const float*)d_in[16];  const float* b2 = (const float*)d_in[17];
    const float* wres = (const float*)d_in[18]; const float* bres = (const float*)d_in[19];
    float* out = (float*)d_out;

    const int smem1 = (TMR * Ndim + 32 * TN) * 4;   // 98304 B
    cudaFuncSetAttribute(k1_fused, cudaFuncAttributeMaxDynamicSharedMemorySize, smem1);

    k0_proj<<<dim3(32, 1, 2), 256>>>(src, tgt, wq, bq, wk, bk, wv, bv);
    k1_fused<<<dim3(Mdim/TMR, Bsz), 256, smem1>>>(src, tgt);
    k2b_mlp<<<dim3(Mdim/32, Bsz), 128>>>(finv, src, wm, bm, w1, b1);
    k3_stats<<<128, 256>>>();
    k4_out<<<dim3(Mdim/32, Bsz), 128>>>(finv, src, w2, b2, wres, bres, out);
    k5_rind<<<dim3(Mdim/8, Bsz), 128>>>(seqv, teqv, perms, out);
}